// round 3
// baseline (speedup 1.0000x reference)
#include <cuda_runtime.h>

#define IN_   26
#define H1_   64
#define H2_   32
#define T_    1000
#define TC_   50
#define ROWS_ 4
#define THREADS_ 256

// shared-memory float offsets (all 16B aligned)
#define OFF_W1X 0                  // 256 x 28
#define OFF_W1H 7168               // 256 x 68
#define OFF_W2  24576              // 128 x 100
#define OFF_B1  37376              // 256
#define OFF_B2  37632              // 128
#define OFF_S1  37760              // 2 x 4 x 68  (h1 double buffer, stride 272)
#define OFF_S2  38304              // 2 x 4 x 100 (h1|h2 concat double buffer, stride 400)
#define OFF_XS  39104              // 4 x (50*28 + 4)
#define OFF_FC  44720              // 4 x 16
#define SMEM_FLOATS 44784

#define S1STR 272                  // floats per ss1 buffer (4 rows x 68)
#define S2STR 400                  // floats per ss2 buffer (4 rows x 100)

typedef unsigned long long u64;

__device__ __forceinline__ void fma2(u64 &d, u64 a, u64 b) {
    asm("fma.rn.f32x2 %0, %1, %2, %0;" : "+l"(d) : "l"(a), "l"(b));
}
__device__ __forceinline__ float lo32(u64 v){ return __uint_as_float((unsigned)v); }
__device__ __forceinline__ float hi32(u64 v){ return __uint_as_float((unsigned)(v >> 32)); }

// Accurate exp(x), immune to -use_fast_math: Cody-Waite reduction + cephes poly.
__device__ __forceinline__ float exp_acc(float x) {
    x = fminf(fmaxf(x, -87.0f), 87.0f);
    float t = fmaf(x, 1.442695040888963f, 12582912.0f);
    float n = t - 12582912.0f;
    float r = fmaf(n, -0.693145751953125f, x);
    r = fmaf(n, -1.42860677e-06f, r);
    float p = 1.9875691500e-4f;
    p = fmaf(p, r, 1.3981999507e-3f);
    p = fmaf(p, r, 8.3334519073e-3f);
    p = fmaf(p, r, 4.1665795894e-2f);
    p = fmaf(p, r, 1.6666665459e-1f);
    p = fmaf(p, r, 5.0000001201e-1f);
    p = fmaf(p, r * r, r);
    p = p + 1.0f;
    int i = (int)n;
    float scale = __int_as_float((i + 127) << 23);
    return p * scale;
}
__device__ __forceinline__ float sigm(float x) {
    float e = exp_acc(-x);
    return __frcp_rn(1.0f + e);
}
__device__ __forceinline__ float tanhx(float x) {
    float u = exp_acc(2.0f * x);
    return (u - 1.0f) * __frcp_rn(u + 1.0f);
}

extern __shared__ float smem[];

__global__ void __launch_bounds__(THREADS_, 1) audiolstm_kernel(
    const float* __restrict__ x,
    const float* __restrict__ w_ih1, const float* __restrict__ w_hh1,
    const float* __restrict__ b_ih1, const float* __restrict__ b_hh1,
    const float* __restrict__ w_ih2, const float* __restrict__ w_hh2,
    const float* __restrict__ b_ih2, const float* __restrict__ b_hh2,
    const float* __restrict__ w_fc1, const float* __restrict__ b_fc1,
    const float* __restrict__ w_fc2, const float* __restrict__ b_fc2,
    float* __restrict__ out)
{
    const int tid = threadIdx.x;
    const int cb  = blockIdx.x;

    float* sw1x = smem + OFF_W1X;
    float* sw1h = smem + OFF_W1H;
    float* sw2  = smem + OFF_W2;
    float* sb1  = smem + OFF_B1;
    float* sb2  = smem + OFF_B2;
    float* ss1  = smem + OFF_S1;
    float* ss2  = smem + OFF_S2;
    float* sxs  = smem + OFF_XS;
    float* sfc  = smem + OFF_FC;

    // ---- one-time weight load / layout (padded, concat, bias-folded) ----
    for (int idx = tid; idx < 256 * 28; idx += THREADS_) {
        int g = idx / 28, i = idx - g * 28;
        sw1x[idx] = (i < IN_) ? w_ih1[g * IN_ + i] : 0.0f;
    }
    for (int idx = tid; idx < 256 * 68; idx += THREADS_) {
        int g = idx / 68, k = idx - g * 68;
        sw1h[idx] = (k < H1_) ? w_hh1[g * H1_ + k] : 0.0f;
    }
    for (int idx = tid; idx < 128 * 100; idx += THREADS_) {
        int g = idx / 100, k = idx - g * 100;
        float v = 0.0f;
        if (k < 64)      v = w_ih2[g * 64 + k];
        else if (k < 96) v = w_hh2[g * 32 + (k - 64)];
        sw2[idx] = v;
    }
    for (int idx = tid; idx < 256; idx += THREADS_) sb1[idx] = b_ih1[idx] + b_hh1[idx];
    for (int idx = tid; idx < 128; idx += THREADS_) sb2[idx] = b_ih2[idx] + b_hh2[idx];
    for (int idx = tid; idx < 544 + 800; idx += THREADS_) ss1[idx] = 0.0f; // zeros ss1+ss2
    for (int idx = tid; idx < 4 * 1404; idx += THREADS_) sxs[idx] = 0.0f; // zeros x staging
    __syncthreads();

    // ---- per-thread role ----
    const int G = tid >> 2;      // LSTM1 hidden unit 0..63
    const int r = tid & 3;       // batch row within CTA
    const int row0 = cb * ROWS_;

    const ulonglong2* wx[4];
    const ulonglong2* wh[4];
    float bias1[4];
#pragma unroll
    for (int g = 0; g < 4; ++g) {
        wx[g] = (const ulonglong2*)(sw1x + (g * 64 + G) * 28);
        wh[g] = (const ulonglong2*)(sw1h + (g * 64 + G) * 68);
        bias1[g] = sb1[g * 64 + G];
    }
    const ulonglong2* w2p[4];
    float bias2[4];
    if (tid < 128) {
        int u = tid >> 2;        // LSTM2 hidden unit 0..31
#pragma unroll
        for (int g = 0; g < 4; ++g) {
            w2p[g] = (const ulonglong2*)(sw2 + (g * 32 + u) * 100);
            bias2[g] = sb2[g * 32 + u];
        }
    }

    float c1 = 0.0f, c2 = 0.0f;
    int a = 0, b = 0;

    for (int tile = 0; tile < T_ / TC_; ++tile) {
        // stage x tile [4 rows][TC steps][26] (coalesced along t)
        for (int idx = tid; idx < ROWS_ * IN_ * TC_; idx += THREADS_) {
            int rr = idx / (IN_ * TC_);
            int q  = idx - rr * (IN_ * TC_);
            int i  = q / TC_, tt = q - i * TC_;
            sxs[rr * 1404 + tt * 28 + i] = x[((row0 + rr) * IN_ + i) * T_ + tile * TC_ + tt];
        }
        __syncthreads();

        for (int tt = 0; tt < TC_; ++tt) {
            // ================= phase 1: LSTM1 cell (all 256 threads) =================
            u64 acc0 = (u64)__float_as_uint(bias1[0]);
            u64 acc1 = (u64)__float_as_uint(bias1[1]);
            u64 acc2 = (u64)__float_as_uint(bias1[2]);
            u64 acc3 = (u64)__float_as_uint(bias1[3]);

            const ulonglong2* xp = (const ulonglong2*)(sxs + r * 1404 + tt * 28);
#pragma unroll
            for (int i2 = 0; i2 < 7; ++i2) {
                ulonglong2 xv = xp[i2];
                ulonglong2 w0 = wx[0][i2]; fma2(acc0, w0.x, xv.x); fma2(acc0, w0.y, xv.y);
                ulonglong2 w1 = wx[1][i2]; fma2(acc1, w1.x, xv.x); fma2(acc1, w1.y, xv.y);
                ulonglong2 w2v = wx[2][i2]; fma2(acc2, w2v.x, xv.x); fma2(acc2, w2v.y, xv.y);
                ulonglong2 w3 = wx[3][i2]; fma2(acc3, w3.x, xv.x); fma2(acc3, w3.y, xv.y);
            }
            const ulonglong2* hp = (const ulonglong2*)(ss1 + a * S1STR + r * 68);
#pragma unroll
            for (int k2 = 0; k2 < 16; ++k2) {
                ulonglong2 hv = hp[k2];
                ulonglong2 w0 = wh[0][k2]; fma2(acc0, w0.x, hv.x); fma2(acc0, w0.y, hv.y);
                ulonglong2 w1 = wh[1][k2]; fma2(acc1, w1.x, hv.x); fma2(acc1, w1.y, hv.y);
                ulonglong2 w2v = wh[2][k2]; fma2(acc2, w2v.x, hv.x); fma2(acc2, w2v.y, hv.y);
                ulonglong2 w3 = wh[3][k2]; fma2(acc3, w3.x, hv.x); fma2(acc3, w3.y, hv.y);
            }
            float g0 = lo32(acc0) + hi32(acc0);
            float g1 = lo32(acc1) + hi32(acc1);
            float g2 = lo32(acc2) + hi32(acc2);
            float g3 = lo32(acc3) + hi32(acc3);
            float iv = sigm(g0), fv = sigm(g1), gv = tanhx(g2), ov = sigm(g3);
            c1 = fv * c1 + iv * gv;
            float h1v = ov * tanhx(c1);
            ss1[(a ^ 1) * S1STR + r * 68 + G] = h1v;   // for next step's gates1
            ss2[b * S2STR + r * 100 + G]      = h1v;   // for this step's gates2
            __syncthreads();

            // ================= phase 2: LSTM2 cell (threads 0..127) =================
            if (tid < 128) {
                u64 d0 = (u64)__float_as_uint(bias2[0]);
                u64 d1 = (u64)__float_as_uint(bias2[1]);
                u64 d2 = (u64)__float_as_uint(bias2[2]);
                u64 d3 = (u64)__float_as_uint(bias2[3]);
                const ulonglong2* sp = (const ulonglong2*)(ss2 + b * S2STR + r * 100);
#pragma unroll
                for (int k2 = 0; k2 < 24; ++k2) {
                    ulonglong2 sv = sp[k2];
                    ulonglong2 q0 = w2p[0][k2]; fma2(d0, q0.x, sv.x); fma2(d0, q0.y, sv.y);
                    ulonglong2 q1 = w2p[1][k2]; fma2(d1, q1.x, sv.x); fma2(d1, q1.y, sv.y);
                    ulonglong2 q2 = w2p[2][k2]; fma2(d2, q2.x, sv.x); fma2(d2, q2.y, sv.y);
                    ulonglong2 q3 = w2p[3][k2]; fma2(d3, q3.x, sv.x); fma2(d3, q3.y, sv.y);
                }
                float e0 = lo32(d0) + hi32(d0);
                float e1 = lo32(d1) + hi32(d1);
                float e2 = lo32(d2) + hi32(d2);
                float e3 = lo32(d3) + hi32(d3);
                float iv2 = sigm(e0), fv2 = sigm(e1), gv2 = tanhx(e2), ov2 = sigm(e3);
                c2 = fv2 * c2 + iv2 * gv2;
                float h2v = ov2 * tanhx(c2);
                ss2[(b ^ 1) * S2STR + r * 100 + 64 + (tid >> 2)] = h2v;  // for next step's gates2
            }
            __syncthreads();
            a ^= 1; b ^= 1;
        }
    }

    // ================= FC head: final h2 is in ss2[b] cols 64..95 =================
    if (tid < 64) {
        int f = tid >> 2;  // 0..15
        const float* hrow = ss2 + b * S2STR + r * 100 + 64;
        float acc = b_fc1[f];
#pragma unroll
        for (int k = 0; k < 32; ++k) acc = fmaf(hrow[k], w_fc1[f * 32 + k], acc);
        sfc[r * 16 + f] = fmaxf(acc, 0.0f);
    }
    __syncthreads();
    if (tid < 40) {
        int o = tid >> 2;  // 0..9
        float acc = b_fc2[o];
#pragma unroll
        for (int k = 0; k < 16; ++k) acc = fmaf(sfc[r * 16 + k], w_fc2[o * 16 + k], acc);
        out[(row0 + r) * 10 + o] = acc;
    }
}

extern "C" void kernel_launch(void* const* d_in, const int* in_sizes, int n_in,
                              void* d_out, int out_size) {
    const float* x     = (const float*)d_in[0];
    const float* w_ih1 = (const float*)d_in[1];
    const float* w_hh1 = (const float*)d_in[2];
    const float* b_ih1 = (const float*)d_in[3];
    const float* b_hh1 = (const float*)d_in[4];
    const float* w_ih2 = (const float*)d_in[5];
    const float* w_hh2 = (const float*)d_in[6];
    const float* b_ih2 = (const float*)d_in[7];
    const float* b_hh2 = (const float*)d_in[8];
    const float* w_fc1 = (const float*)d_in[9];
    const float* b_fc1 = (const float*)d_in[10];
    const float* w_fc2 = (const float*)d_in[11];
    const float* b_fc2 = (const float*)d_in[12];
    float* out = (float*)d_out;

    int Bv = in_sizes[0] / (IN_ * T_);       // 512
    int grid = Bv / ROWS_;                   // 128 CTAs
    size_t smbytes = SMEM_FLOATS * sizeof(float);  // ~175 KB
    cudaFuncSetAttribute(audiolstm_kernel,
                         cudaFuncAttributeMaxDynamicSharedMemorySize, (int)smbytes);
    audiolstm_kernel<<<grid, THREADS_, smbytes>>>(
        x, w_ih1, w_hh1, b_ih1, b_hh1,
        w_ih2, w_hh2, b_ih2, b_hh2,
        w_fc1, b_fc1, w_fc2, b_fc2, out);
}

// round 4
// speedup vs baseline: 1.4133x; 1.4133x over previous
#include <cuda_runtime.h>

#define IN_   26
#define H1_   64
#define H2_   32
#define T_    1000
#define TC_   50
#define ROWS_ 4
#define THREADS_ 384

typedef unsigned long long u64;

__device__ __forceinline__ void fma2(u64 &d, u64 a, u64 b) {
    asm("fma.rn.f32x2 %0, %1, %2, %0;" : "+l"(d) : "l"(a), "l"(b));
}
__device__ __forceinline__ float lo32(u64 v){ return __uint_as_float((unsigned)v); }
__device__ __forceinline__ float hi32(u64 v){ return __uint_as_float((unsigned)(v >> 32)); }
__device__ __forceinline__ u64 packf(float lo, float hi){
    return ((u64)__float_as_uint(hi) << 32) | (u64)__float_as_uint(lo);
}

// Accurate exp(x): Cody-Waite reduction + cephes poly (immune to fast-math).
__device__ __forceinline__ float exp_acc(float x) {
    x = fminf(fmaxf(x, -87.0f), 87.0f);
    float t = fmaf(x, 1.442695040888963f, 12582912.0f);
    float n = t - 12582912.0f;
    float r = fmaf(n, -0.693145751953125f, x);
    r = fmaf(n, -1.42860677e-06f, r);
    float p = 1.9875691500e-4f;
    p = fmaf(p, r, 1.3981999507e-3f);
    p = fmaf(p, r, 8.3334519073e-3f);
    p = fmaf(p, r, 4.1665795894e-2f);
    p = fmaf(p, r, 1.6666665459e-1f);
    p = fmaf(p, r, 5.0000001201e-1f);
    p = fmaf(p, r * r, r);
    p = p + 1.0f;
    int i = (int)n;
    float scale = __int_as_float((i + 127) << 23);
    return p * scale;
}
__device__ __forceinline__ float tanhx(float x) {
    float u = exp_acc(2.0f * x);
    return (u - 1.0f) * __frcp_rn(u + 1.0f);
}

// smem layout (floats)
__shared__ float xs[ROWS_ * TC_ * 28];   // 5600: [r][tt][28]
__shared__ float h1s[2 * ROWS_ * 68];    // 544:  [buf][r][68] (64 used)
__shared__ float h2s[2 * ROWS_ * 36];    // 288:  [buf][r][36] (32 used)
__shared__ float sfc[64];                // FC1 intermediates [r][16]

__global__ void __launch_bounds__(THREADS_, 1) audiolstm_kernel(
    const float* __restrict__ x,
    const float* __restrict__ w_ih1, const float* __restrict__ w_hh1,
    const float* __restrict__ b_ih1, const float* __restrict__ b_hh1,
    const float* __restrict__ w_ih2, const float* __restrict__ w_hh2,
    const float* __restrict__ b_ih2, const float* __restrict__ b_hh2,
    const float* __restrict__ w_fc1, const float* __restrict__ b_fc1,
    const float* __restrict__ w_fc2, const float* __restrict__ b_fc2,
    float* __restrict__ out)
{
    const int tid  = threadIdx.x;
    const int row0 = blockIdx.x * ROWS_;
    const int lane4 = tid & 3;              // gate index within unit quad
    const bool p1 = (tid < 256);

    // ---- register-resident weights (union'd across the two roles) ----
    u64 wu[48];
    float biasv;
    if (p1) {
        const int G = tid >> 2;                 // LSTM1 unit 0..63
        const int row = lane4 * 64 + G;         // gate row in [0,256)
        const float* wi = w_ih1 + row * IN_;
        const float* wh = w_hh1 + row * H1_;
#pragma unroll
        for (int p = 0; p < 13; ++p) wu[p] = packf(wi[2*p], wi[2*p+1]);  // k 0..25
        wu[13] = 0ull;                                                    // k 26,27 pad
#pragma unroll
        for (int p = 0; p < 32; ++p) wu[14+p] = packf(wh[2*p], wh[2*p+1]); // k 0..63
        wu[46] = 0ull; wu[47] = 0ull;
        biasv = b_ih1[row] + b_hh1[row];
    } else {
        const int J = (tid - 256) >> 2;         // LSTM2 unit 0..31
        const int row = lane4 * 32 + J;         // gate row in [0,128)
        const float* wi = w_ih2 + row * H1_;
        const float* wh = w_hh2 + row * H2_;
#pragma unroll
        for (int p = 0; p < 32; ++p) wu[p] = packf(wi[2*p], wi[2*p+1]);   // h1-part
#pragma unroll
        for (int p = 0; p < 16; ++p) wu[32+p] = packf(wh[2*p], wh[2*p+1]); // h2-part
        biasv = b_ih2[row] + b_hh2[row];
    }
    const u64 bias_u = (u64)__float_as_uint(biasv);
    const int unitG = p1 ? (tid >> 2) : ((tid - 256) >> 2);

    // zero h state buffers
    for (int i = tid; i < 2 * ROWS_ * 68; i += THREADS_) h1s[i] = 0.0f;
    for (int i = tid; i < 2 * ROWS_ * 36; i += THREADS_) h2s[i] = 0.0f;

    float cst = 0.0f;     // cell state for (my layer, row = lane4)
    int pb = 0;           // parity: phase1 reads h1s[pb], writes h1s[pb^1];
                          // phase2 reads h1s[pb^1] + h2s[pb], writes h2s[pb^1]

    for (int tile = 0; tile < T_ / TC_; ++tile) {
        // stage x tile: [r][tt][28], coalesced along t (tt innermost in idx)
        for (int idx = tid; idx < ROWS_ * 28 * TC_; idx += THREADS_) {
            int rr = idx / (28 * TC_);
            int rem = idx - rr * (28 * TC_);
            int i  = rem / TC_, tt = rem - i * TC_;
            float v = 0.0f;
            if (i < IN_) v = x[((row0 + rr) * IN_ + i) * T_ + tile * TC_ + tt];
            xs[(rr * TC_ + tt) * 28 + i] = v;
        }
        __syncthreads();

        for (int tt = 0; tt < TC_; ++tt) {
            if (p1) {
                // ---------- LSTM1: dot products for 4 rows ----------
                float gate[4];
#pragma unroll
                for (int r = 0; r < 4; ++r) {
                    u64 a = bias_u;
                    const ulonglong2* xp = (const ulonglong2*)(xs + (r * TC_ + tt) * 28);
#pragma unroll
                    for (int p = 0; p < 7; ++p) {
                        ulonglong2 v = xp[p];
                        fma2(a, wu[2*p],   v.x);
                        fma2(a, wu[2*p+1], v.y);
                    }
                    const ulonglong2* hp = (const ulonglong2*)(h1s + (pb * ROWS_ + r) * 68);
#pragma unroll
                    for (int p = 0; p < 16; ++p) {
                        ulonglong2 v = hp[p];
                        fma2(a, wu[14 + 2*p], v.x);
                        fma2(a, wu[15 + 2*p], v.y);
                    }
                    gate[r] = lo32(a) + hi32(a);
                }
                // own-gate activation (lane4==2 -> tanh, else sigmoid)
                const bool isg = (lane4 == 2);
                float act[4];
#pragma unroll
                for (int r = 0; r < 4; ++r) {
                    float u = exp_acc(isg ? 2.0f * gate[r] : -gate[r]);
                    float t = __frcp_rn(1.0f + u);
                    act[r] = isg ? (u - 1.0f) * t : t;
                }
                // quad gather: lane g keeps row r==g
                float iv, fv, gv, ov;
#pragma unroll
                for (int k = 0; k < 4; ++k) {
                    float vi = __shfl_sync(0xffffffffu, act[k], 0, 4);
                    float vf = __shfl_sync(0xffffffffu, act[k], 1, 4);
                    float vg = __shfl_sync(0xffffffffu, act[k], 2, 4);
                    float vo = __shfl_sync(0xffffffffu, act[k], 3, 4);
                    if (lane4 == k) { iv = vi; fv = vf; gv = vg; ov = vo; }
                }
                cst = fmaf(fv, cst, iv * gv);
                float hv = ov * tanhx(cst);
                h1s[((pb ^ 1) * ROWS_ + lane4) * 68 + unitG] = hv;
            }
            __syncthreads();
            if (!p1) {
                // ---------- LSTM2 (overlaps next step's LSTM1) ----------
                float gate[4];
#pragma unroll
                for (int r = 0; r < 4; ++r) {
                    u64 a = bias_u;
                    const ulonglong2* hp1 = (const ulonglong2*)(h1s + ((pb ^ 1) * ROWS_ + r) * 68);
#pragma unroll
                    for (int p = 0; p < 16; ++p) {
                        ulonglong2 v = hp1[p];
                        fma2(a, wu[2*p],   v.x);
                        fma2(a, wu[2*p+1], v.y);
                    }
                    const ulonglong2* hp2 = (const ulonglong2*)(h2s + (pb * ROWS_ + r) * 36);
#pragma unroll
                    for (int p = 0; p < 8; ++p) {
                        ulonglong2 v = hp2[p];
                        fma2(a, wu[32 + 2*p], v.x);
                        fma2(a, wu[33 + 2*p], v.y);
                    }
                    gate[r] = lo32(a) + hi32(a);
                }
                const bool isg = (lane4 == 2);
                float act[4];
#pragma unroll
                for (int r = 0; r < 4; ++r) {
                    float u = exp_acc(isg ? 2.0f * gate[r] : -gate[r]);
                    float t = __frcp_rn(1.0f + u);
                    act[r] = isg ? (u - 1.0f) * t : t;
                }
                float iv, fv, gv, ov;
#pragma unroll
                for (int k = 0; k < 4; ++k) {
                    float vi = __shfl_sync(0xffffffffu, act[k], 0, 4);
                    float vf = __shfl_sync(0xffffffffu, act[k], 1, 4);
                    float vg = __shfl_sync(0xffffffffu, act[k], 2, 4);
                    float vo = __shfl_sync(0xffffffffu, act[k], 3, 4);
                    if (lane4 == k) { iv = vi; fv = vf; gv = vg; ov = vo; }
                }
                cst = fmaf(fv, cst, iv * gv);
                float hv = ov * tanhx(cst);
                h2s[((pb ^ 1) * ROWS_ + lane4) * 36 + unitG] = hv;
            }
            pb ^= 1;
        }
    }

    __syncthreads();   // make last phase2 writes visible
    // final h2 lives in h2s[pb] (last write was to buffer (999+1)%2 == pb after flips)

    // ---------------- FC head ----------------
    if (tid < 64) {
        int r = tid & 3, f = tid >> 2;   // f 0..15
        const float* hrow = h2s + (pb * ROWS_ + r) * 36;
        float acc = b_fc1[f];
#pragma unroll
        for (int k = 0; k < H2_; ++k) acc = fmaf(hrow[k], w_fc1[f * H2_ + k], acc);
        sfc[r * 16 + f] = fmaxf(acc, 0.0f);
    }
    __syncthreads();
    if (tid < 40) {
        int r = tid & 3, o = tid >> 2;   // o 0..9
        float acc = b_fc2[o];
#pragma unroll
        for (int k = 0; k < 16; ++k) acc = fmaf(sfc[r * 16 + k], w_fc2[o * 16 + k], acc);
        out[(row0 + r) * 10 + o] = acc;
    }
}

extern "C" void kernel_launch(void* const* d_in, const int* in_sizes, int n_in,
                              void* d_out, int out_size) {
    const float* x     = (const float*)d_in[0];
    const float* w_ih1 = (const float*)d_in[1];
    const float* w_hh1 = (const float*)d_in[2];
    const float* b_ih1 = (const float*)d_in[3];
    const float* b_hh1 = (const float*)d_in[4];
    const float* w_ih2 = (const float*)d_in[5];
    const float* w_hh2 = (const float*)d_in[6];
    const float* b_ih2 = (const float*)d_in[7];
    const float* b_hh2 = (const float*)d_in[8];
    const float* w_fc1 = (const float*)d_in[9];
    const float* b_fc1 = (const float*)d_in[10];
    const float* w_fc2 = (const float*)d_in[11];
    const float* b_fc2 = (const float*)d_in[12];
    float* out = (float*)d_out;

    int Bv = in_sizes[0] / (IN_ * T_);       // 512
    int grid = Bv / ROWS_;                   // 128 CTAs
    audiolstm_kernel<<<grid, THREADS_>>>(
        x, w_ih1, w_hh1, b_ih1, b_hh1,
        w_ih2, w_hh2, b_ih2, b_hh2,
        w_fc1, b_fc1, w_fc2, b_fc2, out);
}

// round 5
// speedup vs baseline: 1.5576x; 1.1021x over previous
#include <cuda_runtime.h>

#define IN_   26
#define H1_   64
#define H2_   32
#define T_    1000
#define TC_   50
#define ROWS_ 4
#define THREADS_ 384

#define L2E_      1.4426950408889634f
#define TWO_L2E_  2.8853900817779268f

typedef unsigned long long u64;

__device__ __forceinline__ void fma2(u64 &d, u64 a, u64 b) {
    asm("fma.rn.f32x2 %0, %1, %2, %0;" : "+l"(d) : "l"(a), "l"(b));
}
__device__ __forceinline__ float lo32(u64 v){ return __uint_as_float((unsigned)v); }
__device__ __forceinline__ float hi32(u64 v){ return __uint_as_float((unsigned)(v >> 32)); }
__device__ __forceinline__ u64 packf(float lo, float hi){
    return ((u64)__float_as_uint(hi) << 32) | (u64)__float_as_uint(lo);
}
__device__ __forceinline__ float ex2a(float x){ float r; asm("ex2.approx.f32 %0, %1;" : "=f"(r) : "f"(x)); return r; }
__device__ __forceinline__ float rcpa(float x){ float r; asm("rcp.approx.f32 %0, %1;" : "=f"(r) : "f"(x)); return r; }

// tanh on true-domain input c (scale inside), inf-safe
__device__ __forceinline__ float tanh_true(float c) {
    float u = ex2a(fminf(TWO_L2E_ * c, 50.0f));
    return (u - 1.0f) * rcpa(u + 1.0f);
}

// smem layout (floats)
__shared__ float xs[ROWS_ * TC_ * 28];   // [r][tt][28]
__shared__ float h1s[2 * ROWS_ * 68];    // [buf][r][68] (64 used)
__shared__ float h2s[2 * ROWS_ * 36];    // [buf][r][36] (32 used)
__shared__ float sfc[64];                // FC1 intermediates [r][16]

__global__ void __launch_bounds__(THREADS_, 1) audiolstm_kernel(
    const float* __restrict__ x,
    const float* __restrict__ w_ih1, const float* __restrict__ w_hh1,
    const float* __restrict__ b_ih1, const float* __restrict__ b_hh1,
    const float* __restrict__ w_ih2, const float* __restrict__ w_hh2,
    const float* __restrict__ b_ih2, const float* __restrict__ b_hh2,
    const float* __restrict__ w_fc1, const float* __restrict__ b_fc1,
    const float* __restrict__ w_fc2, const float* __restrict__ b_fc2,
    float* __restrict__ out)
{
    const int tid  = threadIdx.x;
    const int row0 = blockIdx.x * ROWS_;
    const int lane4 = tid & 3;              // gate index within unit quad
    const bool p1 = (tid < 256);

    // ---- register-resident weights, PRESCALED by log2e ----
    u64 wu[48];
    float biasv;
    if (p1) {
        const int G = tid >> 2;                 // LSTM1 unit 0..63
        const int row = lane4 * 64 + G;         // gate row in [0,256)
        const float* wi = w_ih1 + row * IN_;
        const float* wh = w_hh1 + row * H1_;
#pragma unroll
        for (int p = 0; p < 13; ++p) wu[p] = packf(wi[2*p] * L2E_, wi[2*p+1] * L2E_);
        wu[13] = 0ull;
#pragma unroll
        for (int p = 0; p < 32; ++p) wu[14+p] = packf(wh[2*p] * L2E_, wh[2*p+1] * L2E_);
        wu[46] = 0ull; wu[47] = 0ull;
        biasv = (b_ih1[row] + b_hh1[row]) * L2E_;
    } else {
        const int J = (tid - 256) >> 2;         // LSTM2 unit 0..31
        const int row = lane4 * 32 + J;         // gate row in [0,128)
        const float* wi = w_ih2 + row * H1_;
        const float* wh = w_hh2 + row * H2_;
#pragma unroll
        for (int p = 0; p < 32; ++p) wu[p] = packf(wi[2*p] * L2E_, wi[2*p+1] * L2E_);
#pragma unroll
        for (int p = 0; p < 16; ++p) wu[32+p] = packf(wh[2*p] * L2E_, wh[2*p+1] * L2E_);
        biasv = (b_ih2[row] + b_hh2[row]) * L2E_;
    }
    const u64 bias_u = (u64)__float_as_uint(biasv);
    const int unitG = p1 ? (tid >> 2) : ((tid - 256) >> 2);
    const bool isg = (lane4 == 2);

    for (int i = tid; i < 2 * ROWS_ * 68; i += THREADS_) h1s[i] = 0.0f;
    for (int i = tid; i < 2 * ROWS_ * 36; i += THREADS_) h2s[i] = 0.0f;

    float cst = 0.0f;
    int pb = 0;

    for (int tile = 0; tile < T_ / TC_; ++tile) {
        for (int idx = tid; idx < ROWS_ * 28 * TC_; idx += THREADS_) {
            int rr = idx / (28 * TC_);
            int rem = idx - rr * (28 * TC_);
            int i  = rem / TC_, tt = rem - i * TC_;
            float v = 0.0f;
            if (i < IN_) v = x[((row0 + rr) * IN_ + i) * T_ + tile * TC_ + tt];
            xs[(rr * TC_ + tt) * 28 + i] = v;
        }
        __syncthreads();

        for (int tt = 0; tt < TC_; ++tt) {
            if (p1) {
                // ---------- LSTM1: dot products for 4 rows (gate domain = x*log2e) ----------
                float a[4];
#pragma unroll
                for (int r = 0; r < 4; ++r) {
                    u64 acc = bias_u;
                    const ulonglong2* xp = (const ulonglong2*)(xs + (r * TC_ + tt) * 28);
#pragma unroll
                    for (int p = 0; p < 7; ++p) {
                        ulonglong2 v = xp[p];
                        fma2(acc, wu[2*p],   v.x);
                        fma2(acc, wu[2*p+1], v.y);
                    }
                    const ulonglong2* hp = (const ulonglong2*)(h1s + (pb * ROWS_ + r) * 68);
#pragma unroll
                    for (int p = 0; p < 16; ++p) {
                        ulonglong2 v = hp[p];
                        fma2(acc, wu[14 + 2*p], v.x);
                        fma2(acc, wu[15 + 2*p], v.y);
                    }
                    float t = lo32(acc) + hi32(acc);
                    // own-gate activation (lane 2 -> tanh, else sigmoid), 2^x domain
                    float u = ex2a(fminf(isg ? 2.0f * t : -t, 50.0f));
                    a[r] = isg ? (u - 1.0f) * rcpa(u + 1.0f) : rcpa(1.0f + u);
                }
                // ---- 4x4 quad transpose (bfly): a[k] becomes gate-k act for row lane4 ----
                {
                    float e0 = __shfl_xor_sync(0xffffffffu, (lane4 & 2) ? a[0] : a[2], 2, 4);
                    float e1 = __shfl_xor_sync(0xffffffffu, (lane4 & 2) ? a[1] : a[3], 2, 4);
                    if (lane4 & 2) { a[0] = e0; a[1] = e1; } else { a[2] = e0; a[3] = e1; }
                    float f0 = __shfl_xor_sync(0xffffffffu, (lane4 & 1) ? a[0] : a[1], 1, 4);
                    float f1 = __shfl_xor_sync(0xffffffffu, (lane4 & 1) ? a[2] : a[3], 1, 4);
                    if (lane4 & 1) { a[0] = f0; a[2] = f1; } else { a[1] = f0; a[3] = f1; }
                }
                cst = fmaf(a[1], cst, a[0] * a[2]);
                float hv = a[3] * tanh_true(cst);
                h1s[((pb ^ 1) * ROWS_ + lane4) * 68 + unitG] = hv;
            }
            __syncthreads();
            if (!p1) {
                // ---------- LSTM2 (overlaps next step's LSTM1) ----------
                float a[4];
#pragma unroll
                for (int r = 0; r < 4; ++r) {
                    u64 acc = bias_u;
                    const ulonglong2* hp1 = (const ulonglong2*)(h1s + ((pb ^ 1) * ROWS_ + r) * 68);
#pragma unroll
                    for (int p = 0; p < 16; ++p) {
                        ulonglong2 v = hp1[p];
                        fma2(acc, wu[2*p],   v.x);
                        fma2(acc, wu[2*p+1], v.y);
                    }
                    const ulonglong2* hp2 = (const ulonglong2*)(h2s + (pb * ROWS_ + r) * 36);
#pragma unroll
                    for (int p = 0; p < 8; ++p) {
                        ulonglong2 v = hp2[p];
                        fma2(acc, wu[32 + 2*p], v.x);
                        fma2(acc, wu[33 + 2*p], v.y);
                    }
                    float t = lo32(acc) + hi32(acc);
                    float u = ex2a(fminf(isg ? 2.0f * t : -t, 50.0f));
                    a[r] = isg ? (u - 1.0f) * rcpa(u + 1.0f) : rcpa(1.0f + u);
                }
                {
                    float e0 = __shfl_xor_sync(0xffffffffu, (lane4 & 2) ? a[0] : a[2], 2, 4);
                    float e1 = __shfl_xor_sync(0xffffffffu, (lane4 & 2) ? a[1] : a[3], 2, 4);
                    if (lane4 & 2) { a[0] = e0; a[1] = e1; } else { a[2] = e0; a[3] = e1; }
                    float f0 = __shfl_xor_sync(0xffffffffu, (lane4 & 1) ? a[0] : a[1], 1, 4);
                    float f1 = __shfl_xor_sync(0xffffffffu, (lane4 & 1) ? a[2] : a[3], 1, 4);
                    if (lane4 & 1) { a[0] = f0; a[2] = f1; } else { a[1] = f0; a[3] = f1; }
                }
                cst = fmaf(a[1], cst, a[0] * a[2]);
                float hv = a[3] * tanh_true(cst);
                h2s[((pb ^ 1) * ROWS_ + lane4) * 36 + unitG] = hv;
            }
            pb ^= 1;
        }
    }

    __syncthreads();

    // ---------------- FC head ----------------
    if (tid < 64) {
        int r = tid & 3, f = tid >> 2;
        const float* hrow = h2s + (pb * ROWS_ + r) * 36;
        float acc = b_fc1[f];
#pragma unroll
        for (int k = 0; k < H2_; ++k) acc = fmaf(hrow[k], w_fc1[f * H2_ + k], acc);
        sfc[r * 16 + f] = fmaxf(acc, 0.0f);
    }
    __syncthreads();
    if (tid < 40) {
        int r = tid & 3, o = tid >> 2;
        float acc = b_fc2[o];
#pragma unroll
        for (int k = 0; k < 16; ++k) acc = fmaf(sfc[r * 16 + k], w_fc2[o * 16 + k], acc);
        out[(row0 + r) * 10 + o] = acc;
    }
}

extern "C" void kernel_launch(void* const* d_in, const int* in_sizes, int n_in,
                              void* d_out, int out_size) {
    const float* x     = (const float*)d_in[0];
    const float* w_ih1 = (const float*)d_in[1];
    const float* w_hh1 = (const float*)d_in[2];
    const float* b_ih1 = (const float*)d_in[3];
    const float* b_hh1 = (const float*)d_in[4];
    const float* w_ih2 = (const float*)d_in[5];
    const float* w_hh2 = (const float*)d_in[6];
    const float* b_ih2 = (const float*)d_in[7];
    const float* b_hh2 = (const float*)d_in[8];
    const float* w_fc1 = (const float*)d_in[9];
    const float* b_fc1 = (const float*)d_in[10];
    const float* w_fc2 = (const float*)d_in[11];
    const float* b_fc2 = (const float*)d_in[12];
    float* out = (float*)d_out;

    int Bv = in_sizes[0] / (IN_ * T_);       // 512
    int grid = Bv / ROWS_;                   // 128 CTAs
    audiolstm_kernel<<<grid, THREADS_>>>(
        x, w_ih1, w_hh1, b_ih1, b_hh1,
        w_ih2, w_hh2, b_ih2, b_hh2,
        w_fc1, b_fc1, w_fc2, b_fc2, out);
}